// round 16
// baseline (speedup 1.0000x reference)
#include <cuda_runtime.h>

// CRF broadcast-add: out[b,l,i,j] = emission[b,l,j] + transition[i,j]
// B=32, L=512, T=64 -> 16384 tiles of 64x64 fp32; here split into 32768
// HALF-tiles (32 i-rows = 512 float4 = 8 KB) with one CTA of 128 threads each.
//
// R15 showed one-shot CTAs beat persistent grid-stride by 6us: CTAs retire
// right after their fire-and-forget store burst, so the HW work distributor
// pipelines bursts continuously. R16 pushes the granularity lever further:
// half-tile CTAs -> 2x finer scheduling quanta, same per-thread recipe
// (1 emission float4, 4 transition float4s in regs, 4 STG.128 stcs stores).

constexpr int Tc = 64;
constexpr int BL = 32 * 512;                  // 16384 tiles
constexpr int HALF_F4 = (Tc * Tc) / 4 / 2;    // 512 float4 per half-tile
constexpr int EM_F4_PER_TILE = Tc / 4;        // 16
constexpr int THREADS = 128;
constexpr int F4_PER_THREAD = HALF_F4 / THREADS;  // 4

__global__ void __launch_bounds__(THREADS, 16)
crf_broadcast_add(const float4* __restrict__ em4,
                  const float4* __restrict__ tr4,
                  float4* __restrict__ out4)
{
    const int t    = threadIdx.x;
    const int cta  = blockIdx.x;               // 0 .. 32767
    const int bl   = cta >> 1;                 // tile index
    const int half = cta & 1;                  // 0: rows 0-31, 1: rows 32-63
    const int j4   = t & (EM_F4_PER_TILE - 1); // t % 16

    // Emission float4 for this tile (same for both halves).
    const float4 e = __ldg(&em4[(size_t)bl * EM_F4_PER_TILE + j4]);

    // This CTA's half of the transition matrix: float4s [half*512 + t + 128k].
    const int trbase = half * HALF_F4 + t;
    float4 tr[F4_PER_THREAD];
#pragma unroll
    for (int k = 0; k < F4_PER_THREAD; ++k)
        tr[k] = __ldg(&tr4[trbase + THREADS * k]);

    float4* __restrict__ o = out4 + (size_t)bl * (2 * HALF_F4) + half * HALF_F4 + t;
#pragma unroll
    for (int k = 0; k < F4_PER_THREAD; ++k) {
        float4 v;
        v.x = e.x + tr[k].x;
        v.y = e.y + tr[k].y;
        v.z = e.z + tr[k].z;
        v.w = e.w + tr[k].w;
        __stcs(o + THREADS * k, v);            // streaming: evict-first
    }
}

extern "C" void kernel_launch(void* const* d_in, const int* in_sizes, int n_in,
                              void* d_out, int out_size)
{
    const float4* em4 = (const float4*)d_in[0];   // emission [B, L, T] fp32
    const float4* tr4 = (const float4*)d_in[1];   // transition [T, T] fp32
    float4* out4      = (float4*)d_out;           // [B, L, T, T] fp32

    crf_broadcast_add<<<BL * 2, THREADS>>>(em4, tr4, out4);  // one half-tile per CTA
}